// round 15
// baseline (speedup 1.0000x reference)
#include <cuda_runtime.h>
#include <cuda_bf16.h>

#define NUM_CLASSES 601
#define OUT_DIM 27
#define PAD_DIM 32          // table rows padded to 32 floats = 128 B = one L1 line
#define CHUNK 32            // rows per warp; CHUNK*OUT_DIM = 864 floats = 3456 B (27 x 128B)
#define WARPS_PER_CTA 8
#define BUILDER_CTAS 76     // 76 CTAs x 8 warps = 608 >= 601 table rows

// Precomputed softmax table: 601 rows x 32 floats (cols 27..31 = 0 padding).
// 601*32*4 = 76,928 B -> L1/L2 resident.
__device__ __align__(128) float g_table[NUM_CLASSES * PAD_DIM];
__device__ int g_ctr;       // zero-initialized at module load; monotonic across replays

// ---------------------------------------------------------------------------
// Fused kernel: table build (CTAs 0..75, one warp per class row) + spin
// barrier + warp-cooperative gather with flat 128B-aligned stores.
//
// Spin-barrier safety:
//  - builder CTAs are bid 0..75 -> all in wave 1 (1184 resident CTAs), so
//    builders always make progress: no deadlock.
//  - on graph replays g_ctr is already >= 76: waiters pass immediately;
//    builders rewrite the identical values (same W) -> benign, deterministic.
//  - L1 is flushed at every launch, so no stale table lines.
// ---------------------------------------------------------------------------
__global__ void __launch_bounds__(256) fused_kernel(
    const int* __restrict__ idx, const float* __restrict__ W,
    float* __restrict__ out, int batch)
{
    const int lane = threadIdx.x & 31;
    const int warp = threadIdx.x >> 5;

    // ---- Phase 1: table build (matches reference: exp / sum(exp)) ----
    if (blockIdx.x < BUILDER_CTAS) {
        int r = blockIdx.x * WARPS_PER_CTA + warp;
        if (r < NUM_CLASSES) {
            float e = 0.0f;
            if (lane < OUT_DIM) e = expf(W[r * OUT_DIM + lane]);
            float s = e;
            #pragma unroll
            for (int off = 16; off > 0; off >>= 1)
                s += __shfl_xor_sync(0xffffffffu, s, off);
            g_table[r * PAD_DIM + lane] = (lane < OUT_DIM) ? (e / s) : 0.0f;
        }
        __syncthreads();                 // all 8 warps' rows written
        if (threadIdx.x == 0) {
            __threadfence();             // publish table to L2 before signaling
            atomicAdd(&g_ctr, 1);
        }
    }

    // ---- Phase 2: spin until table is published (thread 0 polls) ----
    if (threadIdx.x == 0) {
        while (atomicAdd(&g_ctr, 0) < BUILDER_CTAS) { }
        __threadfence();
    }
    __syncthreads();

    // ---- Phase 3: gather (unchanged R14 winner body) ----
    const long long base = ((long long)blockIdx.x * WARPS_PER_CTA + warp) * CHUNK;
    if (base >= batch) return;

    const long long nrows = batch - base;   // >= 1

    if (nrows >= CHUNK) {
        // fast path: full 32-row chunk, 27 flat 128B-aligned store groups
        int mi = idx[base + lane];
        float* o = out + base * OUT_DIM;    // 3456*k bytes -> 128B aligned

        #pragma unroll 9
        for (int j = 0; j < OUT_DIM; j++) {
            int e = 32 * j + lane;          // 0..863
            int row = e / 27;               // 0..31 (mul-shift)
            int col = e - row * 27;
            int r = __shfl_sync(0xffffffffu, mi, row);
            o[e] = g_table[r * PAD_DIM + col];
        }
    } else {
        // tail chunk (not taken for batch % 256 == 0, kept for safety)
        int mi = 0;
        if (base + lane < batch) mi = idx[base + lane];
        float* orow = out + base * OUT_DIM + lane;
        int n = (int)nrows;
        for (int j = 0; j < n; j++) {
            int rj = __shfl_sync(0xffffffffu, mi, j);
            float v = g_table[rj * PAD_DIM + lane];
            if (lane < OUT_DIM) orow[j * OUT_DIM] = v;
        }
    }
}

extern "C" void kernel_launch(void* const* d_in, const int* in_sizes, int n_in,
                              void* d_out, int out_size) {
    const int* idx;
    const float* W;
    int batch;
    if (in_sizes[0] == NUM_CLASSES * OUT_DIM) {
        W = (const float*)d_in[0];
        idx = (const int*)d_in[1];
        batch = in_sizes[1];
    } else {
        idx = (const int*)d_in[0];
        W = (const float*)d_in[1];
        batch = in_sizes[0];
    }

    // 8 warps/block, 32 rows/warp -> 256 rows per block
    long long nblocks = ((long long)batch + (WARPS_PER_CTA * CHUNK - 1)) / (WARPS_PER_CTA * CHUNK);
    fused_kernel<<<(int)nblocks, 256>>>(idx, W, (float*)d_out, batch);
}

// round 16
// speedup vs baseline: 1.7959x; 1.7959x over previous
#include <cuda_runtime.h>
#include <cuda_bf16.h>

#define NUM_CLASSES 601
#define OUT_DIM 27
#define PAD_DIM 32          // table rows padded to 32 floats = 128 B = one L1 line
#define CHUNK 32            // rows per warp; CHUNK*OUT_DIM = 864 floats = 3456 B (27 x 128B)
#define WARPS_PER_CTA 8

// Precomputed softmax table: 601 rows x 32 floats (cols 27..31 = 0 padding).
// 601*32*4 = 76,928 B -> L1/L2 resident.
__device__ __align__(128) float g_table[NUM_CLASSES * PAD_DIM];

// ---------------------------------------------------------------------------
// Kernel A: build softmax table. 8 warps/block, one warp per class row.
// Matches reference exactly: probs = exp(logits) / sum(exp(logits)).
// Publishes the table then fires the PDL trigger so kernel B's grid-sync
// releases as early as possible.
// ---------------------------------------------------------------------------
__global__ void softmax_table_kernel(const float* __restrict__ W) {
    int r = blockIdx.x * WARPS_PER_CTA + (threadIdx.x >> 5);
    int c = threadIdx.x & 31;
    if (r < NUM_CLASSES) {
        float e = 0.0f;
        if (c < OUT_DIM) e = expf(W[r * OUT_DIM + c]);
        float s = e;
        #pragma unroll
        for (int off = 16; off > 0; off >>= 1)
            s += __shfl_xor_sync(0xffffffffu, s, off);
        g_table[r * PAD_DIM + c] = (c < OUT_DIM) ? (e / s) : 0.0f;
    }
    __threadfence();                               // publish table device-wide
    cudaTriggerProgrammaticLaunchCompletion();     // release dependent kernel
}

// ---------------------------------------------------------------------------
// Kernel B: warp-cooperative gather with flat 128B-aligned stores (R14 body).
// Launched with PDL: the prologue (index computation + idx LDG, independent
// of the table) overlaps kernel A; cudaGridDependencySynchronize() gates only
// the table reads.
// ---------------------------------------------------------------------------
__global__ void __launch_bounds__(256) gather_flat_kernel(
    const int* __restrict__ idx, float* __restrict__ out, int batch)
{
    const int lane = threadIdx.x & 31;
    const int warp = threadIdx.x >> 5;
    const long long base = ((long long)blockIdx.x * WARPS_PER_CTA + warp) * CHUNK;
    if (base >= batch) {
        cudaGridDependencySynchronize();
        return;
    }

    const long long nrows = batch - base;   // >= 1

    if (nrows >= CHUNK) {
        // prologue: idx load does NOT depend on kernel A -> issue before sync
        int mi = idx[base + lane];
        float* o = out + base * OUT_DIM;    // 3456*k bytes -> 128B aligned

        cudaGridDependencySynchronize();    // wait for table publication

        #pragma unroll 9
        for (int j = 0; j < OUT_DIM; j++) {
            int e = 32 * j + lane;          // 0..863
            int row = e / 27;               // 0..31 (mul-shift)
            int col = e - row * 27;
            int r = __shfl_sync(0xffffffffu, mi, row);
            o[e] = g_table[r * PAD_DIM + col];
        }
    } else {
        // tail chunk (not taken when batch % 256 == 0; kept for safety)
        int mi = 0;
        if (base + lane < batch) mi = idx[base + lane];
        cudaGridDependencySynchronize();
        float* orow = out + base * OUT_DIM + lane;
        int n = (int)nrows;
        for (int j = 0; j < n; j++) {
            int rj = __shfl_sync(0xffffffffu, mi, j);
            float v = g_table[rj * PAD_DIM + lane];
            if (lane < OUT_DIM) orow[j * OUT_DIM] = v;
        }
    }
}

extern "C" void kernel_launch(void* const* d_in, const int* in_sizes, int n_in,
                              void* d_out, int out_size) {
    const int* idx;
    const float* W;
    int batch;
    if (in_sizes[0] == NUM_CLASSES * OUT_DIM) {
        W = (const float*)d_in[0];
        idx = (const int*)d_in[1];
        batch = in_sizes[1];
    } else {
        idx = (const int*)d_in[0];
        W = (const float*)d_in[1];
        batch = in_sizes[0];
    }

    softmax_table_kernel<<<(NUM_CLASSES + WARPS_PER_CTA - 1) / WARPS_PER_CTA, 256>>>(W);

    // Kernel B with programmatic dependent launch on kernel A.
    long long nblocks = ((long long)batch + (WARPS_PER_CTA * CHUNK - 1)) / (WARPS_PER_CTA * CHUNK);

    cudaLaunchConfig_t cfg = {};
    cfg.gridDim = dim3((unsigned)nblocks, 1, 1);
    cfg.blockDim = dim3(256, 1, 1);
    cfg.dynamicSmemBytes = 0;
    cfg.stream = 0;
    cudaLaunchAttribute attrs[1];
    attrs[0].id = cudaLaunchAttributeProgrammaticStreamSerialization;
    attrs[0].val.programmaticStreamSerializationAllowed = 1;
    cfg.attrs = attrs;
    cfg.numAttrs = 1;

    cudaLaunchKernelEx(&cfg, gather_flat_kernel, idx, (float*)d_out, batch);
}

// round 17
// speedup vs baseline: 1.8877x; 1.0511x over previous
#include <cuda_runtime.h>
#include <cuda_bf16.h>

#define NUM_CLASSES 601
#define OUT_DIM 27
#define PAD_DIM 32          // table rows padded to 32 floats = 128 B = one L1 line
#define CHUNK 32            // rows per warp; CHUNK*OUT_DIM = 864 floats = 3456 B (27 x 128B)
#define WARPS_PER_CTA 8

// Precomputed softmax table: 601 rows x 32 floats (cols 27..31 = 0 padding).
// 601*32*4 = 76,928 B -> L1/L2 resident.
__device__ __align__(128) float g_table[NUM_CLASSES * PAD_DIM];

// ---------------------------------------------------------------------------
// Kernel A: build softmax table. 8 warps/block, one warp per class row.
// Matches reference exactly: probs = exp(logits) / sum(exp(logits)).
// ---------------------------------------------------------------------------
__global__ void softmax_table_kernel(const float* __restrict__ W) {
    int r = blockIdx.x * WARPS_PER_CTA + (threadIdx.x >> 5);
    int c = threadIdx.x & 31;
    if (r < NUM_CLASSES) {
        float e = 0.0f;
        if (c < OUT_DIM) e = expf(W[r * OUT_DIM + c]);
        float s = e;
        #pragma unroll
        for (int off = 16; off > 0; off >>= 1)
            s += __shfl_xor_sync(0xffffffffu, s, off);
        g_table[r * PAD_DIM + c] = (c < OUT_DIM) ? (e / s) : 0.0f;
    }
    __threadfence();                               // publish table device-wide
    cudaTriggerProgrammaticLaunchCompletion();     // release dependent kernel
}

// ---------------------------------------------------------------------------
// Kernel B: warp-cooperative gather, flat 128B-aligned stores (R14 winner),
// now with explicit 9-wide load batching (MLP ~9 instead of ~2-3) and
// streaming stores (__stcs: output is write-once, keep it out of L2's way).
// Per 32-row chunk: 27 flat groups; group j -> element e = 32j+lane,
// row = e/27 (shfl source), col = e%27; 1 shfl + 1 L1-resident gather LDG
// (~2.15 lines) + 1 fully-coalesced aligned STG per group.
// ---------------------------------------------------------------------------
__global__ void __launch_bounds__(256) gather_flat_kernel(
    const int* __restrict__ idx, float* __restrict__ out, int batch)
{
    const int lane = threadIdx.x & 31;
    const int warp = threadIdx.x >> 5;
    const long long base = ((long long)blockIdx.x * WARPS_PER_CTA + warp) * CHUNK;
    if (base >= batch) {
        cudaGridDependencySynchronize();
        return;
    }

    const long long nrows = batch - base;   // >= 1

    if (nrows >= CHUNK) {
        // prologue overlaps kernel A via PDL: idx load is table-independent
        int mi = idx[base + lane];
        float* o = out + base * OUT_DIM;    // 3456*k bytes -> 128B aligned

        cudaGridDependencySynchronize();    // wait for table publication

        #pragma unroll
        for (int b = 0; b < 3; b++) {
            float v[9];
            // batch of 9 independent gathers -> 9 loads in flight
            #pragma unroll
            for (int j3 = 0; j3 < 9; j3++) {
                int e = 32 * (b * 9 + j3) + lane;   // 0..863
                int row = e / 27;                   // mul-shift
                int col = e - row * 27;
                int r = __shfl_sync(0xffffffffu, mi, row);
                v[j3] = g_table[r * PAD_DIM + col];
            }
            // then 9 streaming stores
            #pragma unroll
            for (int j3 = 0; j3 < 9; j3++) {
                int e = 32 * (b * 9 + j3) + lane;
                __stcs(o + e, v[j3]);
            }
        }
    } else {
        // tail chunk (not taken when batch % 256 == 0; kept for safety)
        int mi = 0;
        if (base + lane < batch) mi = idx[base + lane];
        cudaGridDependencySynchronize();
        float* orow = out + base * OUT_DIM + lane;
        int n = (int)nrows;
        for (int j = 0; j < n; j++) {
            int rj = __shfl_sync(0xffffffffu, mi, j);
            float v = g_table[rj * PAD_DIM + lane];
            if (lane < OUT_DIM) orow[j * OUT_DIM] = v;
        }
    }
}

extern "C" void kernel_launch(void* const* d_in, const int* in_sizes, int n_in,
                              void* d_out, int out_size) {
    const int* idx;
    const float* W;
    int batch;
    if (in_sizes[0] == NUM_CLASSES * OUT_DIM) {
        W = (const float*)d_in[0];
        idx = (const int*)d_in[1];
        batch = in_sizes[1];
    } else {
        idx = (const int*)d_in[0];
        W = (const float*)d_in[1];
        batch = in_sizes[0];
    }

    softmax_table_kernel<<<(NUM_CLASSES + WARPS_PER_CTA - 1) / WARPS_PER_CTA, 256>>>(W);

    // Kernel B with programmatic dependent launch on kernel A.
    long long nblocks = ((long long)batch + (WARPS_PER_CTA * CHUNK - 1)) / (WARPS_PER_CTA * CHUNK);

    cudaLaunchConfig_t cfg = {};
    cfg.gridDim = dim3((unsigned)nblocks, 1, 1);
    cfg.blockDim = dim3(256, 1, 1);
    cfg.dynamicSmemBytes = 0;
    cfg.stream = 0;
    cudaLaunchAttribute attrs[1];
    attrs[0].id = cudaLaunchAttributeProgrammaticStreamSerialization;
    attrs[0].val.programmaticStreamSerializationAllowed = 1;
    cfg.attrs = attrs;
    cfg.numAttrs = 1;

    cudaLaunchKernelEx(&cfg, gather_flat_kernel, idx, (float*)d_out, batch);
}